// round 3
// baseline (speedup 1.0000x reference)
#include <cuda_runtime.h>
#include <cuda_bf16.h>
#include <cstdint>

// Problem sizes (fixed by the reference)
#define SEQ_LEN   32768
#define IN_SZ     256
#define HID       512
#define OUT_SZ    256

// Scratch: A = X@Wx^T + bh  [SEQ_LEN, HID], H = hidden history [SEQ_LEN, HID]
__device__ __align__(16) float g_A[SEQ_LEN * HID];
__device__ __align__(16) float g_H[SEQ_LEN * HID];

// ---------------------------------------------------------------------------
// Generic tiled GEMM: C[M,N] = Am[M,K] @ Bm[N,K]^T + bias[N]
// 64x64 tile, BK=16, 256 threads, 4x4 micro-tile per thread.
// M % 64 == 0, N % 64 == 0, K % 16 == 0 (true for all our shapes).
// ---------------------------------------------------------------------------
__global__ __launch_bounds__(256) void gemm_abt_bias(
    const float* __restrict__ Am, const float* __restrict__ Bm,
    const float* __restrict__ bias, float* __restrict__ C,
    int M, int N, int K)
{
    __shared__ float As[16][65];
    __shared__ float Bs[16][65];

    const int tid = threadIdx.x;
    const int bm = blockIdx.y * 64;
    const int bn = blockIdx.x * 64;
    const int tx = tid & 15;   // n sub-tile
    const int ty = tid >> 4;   // m sub-tile
    const int lr = tid >> 2;         // 0..63: row within tile for loads
    const int lk = (tid & 3) * 4;    // k offset (float4 granularity)

    float acc[4][4] = {};

    for (int k0 = 0; k0 < K; k0 += 16) {
        float4 av = *(const float4*)&Am[(size_t)(bm + lr) * K + k0 + lk];
        float4 bv = *(const float4*)&Bm[(size_t)(bn + lr) * K + k0 + lk];
        As[lk + 0][lr] = av.x; As[lk + 1][lr] = av.y;
        As[lk + 2][lr] = av.z; As[lk + 3][lr] = av.w;
        Bs[lk + 0][lr] = bv.x; Bs[lk + 1][lr] = bv.y;
        Bs[lk + 2][lr] = bv.z; Bs[lk + 3][lr] = bv.w;
        __syncthreads();

        #pragma unroll
        for (int kk = 0; kk < 16; kk++) {
            float ar[4], br[4];
            #pragma unroll
            for (int i = 0; i < 4; i++) ar[i] = As[kk][ty * 4 + i];
            #pragma unroll
            for (int i = 0; i < 4; i++) br[i] = Bs[kk][tx * 4 + i];
            #pragma unroll
            for (int i = 0; i < 4; i++)
                #pragma unroll
                for (int jj = 0; jj < 4; jj++)
                    acc[i][jj] = fmaf(ar[i], br[jj], acc[i][jj]);
        }
        __syncthreads();
    }

    float bv[4];
    #pragma unroll
    for (int jj = 0; jj < 4; jj++) bv[jj] = bias[bn + tx * 4 + jj];

    #pragma unroll
    for (int i = 0; i < 4; i++) {
        #pragma unroll
        for (int jj = 0; jj < 4; jj++) {
            C[(size_t)(bm + ty * 4 + i) * N + (bn + tx * 4 + jj)] = acc[i][jj] + bv[jj];
        }
    }
}

// ---------------------------------------------------------------------------
// Serial recurrence over 32768 steps on an 8-CTA cluster.
//
// CTA c owns h rows [c*64, (c+1)*64). 512 threads/CTA:
//   jl = tid>>3 (output row within slice), chunk = tid&7 (k-chunk of 64).
// Each thread holds 64 Wh weights in registers (as 16 float4, bank-rotated
// by `chunk` in float4 units so the 8 chunks of a warp hit disjoint smem
// banks on every LDS.128).
// Per step:
//   partial dot (64 FFMA) -> shfl_xor reduce over the 8 chunk lanes ->
//   tanh(acc + A[t][j]) -> each lane stores the result into peer CTA
//   `chunk`'s h buffer via DSMEM (so all 8 peers get all 512 values) ->
//   barrier.cluster (release/acquire orders the DSMEM stores).
// Double-buffered h so one barrier per step suffices.
// ---------------------------------------------------------------------------
__global__ void __cluster_dims__(8, 1, 1) __launch_bounds__(512, 1)
rnn_scan_kernel(const float* __restrict__ Wh,
                const float* __restrict__ A,
                float* __restrict__ H)
{
    __shared__ __align__(16) float hbuf[2][HID];

    const int tid = threadIdx.x;
    uint32_t rank;
    asm("mov.u32 %0, %%cluster_ctarank;" : "=r"(rank));

    const int chunk = tid & 7;        // which 64-wide k chunk
    const int jl = tid >> 3;          // 0..63 local output row
    const int j = (int)rank * 64 + jl;

    // Load this thread's 64 weights (16 float4), with per-chunk rotation.
    float4 w4[16];
    const float4* Wh4 = (const float4*)Wh;  // row j = 128 float4
    #pragma unroll
    for (int q = 0; q < 16; q++) {
        int i4 = chunk * 16 + ((q + chunk) & 15);
        w4[q] = Wh4[(size_t)j * 128 + i4];
    }

    // Init both h buffers to zero (h0 = 0).
    hbuf[0][tid] = 0.0f;
    hbuf[1][tid] = 0.0f;

    // Cluster barrier: everyone's buffers are zeroed before any remote store.
    asm volatile("barrier.cluster.arrive.aligned;" ::: "memory");
    asm volatile("barrier.cluster.wait.aligned;"   ::: "memory");

    // Destination byte offsets inside hbuf for the remote store (both buffers).
    uint32_t dst0 = (uint32_t)__cvta_generic_to_shared(&hbuf[0][j]);
    uint32_t dst1 = (uint32_t)__cvta_generic_to_shared(&hbuf[1][j]);

    int p = 0;
    for (int t = 0; t < SEQ_LEN; t++) {
        // Prefetch the input-projection term (independent of the dot product).
        float a = A[t * HID + j];

        const float4* h4 = (const float4*)hbuf[p];
        float a0 = 0.f, a1 = 0.f, a2 = 0.f, a3 = 0.f;
        #pragma unroll
        for (int q = 0; q < 16; q++) {
            int i4 = chunk * 16 + ((q + chunk) & 15);
            float4 hv = h4[i4];
            float4 wv = w4[q];
            a0 = fmaf(wv.x, hv.x, a0);
            a1 = fmaf(wv.y, hv.y, a1);
            a2 = fmaf(wv.z, hv.z, a2);
            a3 = fmaf(wv.w, hv.w, a3);
        }
        float acc = (a0 + a1) + (a2 + a3);

        // Reduce across the 8 chunk lanes (they are lanes [g*8, g*8+8) of a warp).
        acc += __shfl_xor_sync(0xffffffffu, acc, 1);
        acc += __shfl_xor_sync(0xffffffffu, acc, 2);
        acc += __shfl_xor_sync(0xffffffffu, acc, 4);

        float hn = tanhf(acc + a);

        // Broadcast: lane with chunk == r delivers h[j] to CTA r's next buffer.
        uint32_t laddr = p ? dst0 : dst1;   // write the 1-p buffer
        uint32_t raddr;
        asm volatile("mapa.shared::cluster.u32 %0, %1, %2;"
                     : "=r"(raddr) : "r"(laddr), "r"(chunk));
        asm volatile("st.shared::cluster.f32 [%0], %1;"
                     :: "r"(raddr), "f"(hn) : "memory");

        // Persist h history for the output GEMM (one lane per j).
        if (chunk == 0) H[t * HID + j] = hn;

        // Release/acquire cluster barrier: orders the DSMEM stores and
        // separates step t's reads of hbuf[p] from step t+1's writes to it.
        asm volatile("barrier.cluster.arrive.aligned;" ::: "memory");
        asm volatile("barrier.cluster.wait.aligned;"   ::: "memory");

        p ^= 1;
    }
}

// ---------------------------------------------------------------------------
// Launch: A-GEMM -> serial scan -> Y-GEMM (same stream, graph-capturable).
// ---------------------------------------------------------------------------
extern "C" void kernel_launch(void* const* d_in, const int* in_sizes, int n_in,
                              void* d_out, int out_size)
{
    const float* x  = (const float*)d_in[0];   // [32768, 256]
    const float* Wx = (const float*)d_in[1];   // [512, 256]
    const float* Wh = (const float*)d_in[2];   // [512, 512]
    const float* Wy = (const float*)d_in[3];   // [256, 512]
    const float* bh = (const float*)d_in[4];   // [512]
    const float* by = (const float*)d_in[5];   // [256]
    float* y = (float*)d_out;                  // [32768*256]

    float* A;
    float* H;
    cudaGetSymbolAddress((void**)&A, g_A);
    cudaGetSymbolAddress((void**)&H, g_H);

    // A = X @ Wx^T + bh : M=SEQ_LEN, N=HID, K=IN_SZ
    gemm_abt_bias<<<dim3(HID / 64, SEQ_LEN / 64), 256>>>(
        x, Wx, bh, A, SEQ_LEN, HID, IN_SZ);

    // Serial scan: 1 cluster of 8 CTAs.
    rnn_scan_kernel<<<8, 512>>>(Wh, A, H);

    // Y = H @ Wy^T + by : M=SEQ_LEN, N=OUT_SZ, K=HID
    gemm_abt_bias<<<dim3(OUT_SZ / 64, SEQ_LEN / 64), 256>>>(
        H, Wy, by, y, SEQ_LEN, OUT_SZ, HID);
}

// round 4
// speedup vs baseline: 2.0882x; 2.0882x over previous
#include <cuda_runtime.h>
#include <cuda_bf16.h>
#include <cstdint>

// Problem sizes (fixed by the reference)
#define SEQ_LEN   32768
#define IN_SZ     256
#define HID       512
#define OUT_SZ    256

// Scratch. g_A padded by 2 rows so the 2-deep A prefetch never reads OOB.
__device__ __align__(16) float g_A[(SEQ_LEN + 2) * HID];
__device__ __align__(16) float g_H[SEQ_LEN * HID];

// ---------------------------------------------------------------------------
// Generic tiled GEMM: C[M,N] = Am[M,K] @ Bm[N,K]^T + bias[N]   (unchanged)
// ---------------------------------------------------------------------------
__global__ __launch_bounds__(256) void gemm_abt_bias(
    const float* __restrict__ Am, const float* __restrict__ Bm,
    const float* __restrict__ bias, float* __restrict__ C,
    int M, int N, int K)
{
    __shared__ float As[16][65];
    __shared__ float Bs[16][65];

    const int tid = threadIdx.x;
    const int bm = blockIdx.y * 64;
    const int bn = blockIdx.x * 64;
    const int tx = tid & 15;
    const int ty = tid >> 4;
    const int lr = tid >> 2;
    const int lk = (tid & 3) * 4;

    float acc[4][4] = {};

    for (int k0 = 0; k0 < K; k0 += 16) {
        float4 av = *(const float4*)&Am[(size_t)(bm + lr) * K + k0 + lk];
        float4 bv = *(const float4*)&Bm[(size_t)(bn + lr) * K + k0 + lk];
        As[lk + 0][lr] = av.x; As[lk + 1][lr] = av.y;
        As[lk + 2][lr] = av.z; As[lk + 3][lr] = av.w;
        Bs[lk + 0][lr] = bv.x; Bs[lk + 1][lr] = bv.y;
        Bs[lk + 2][lr] = bv.z; Bs[lk + 3][lr] = bv.w;
        __syncthreads();

        #pragma unroll
        for (int kk = 0; kk < 16; kk++) {
            float ar[4], br[4];
            #pragma unroll
            for (int i = 0; i < 4; i++) ar[i] = As[kk][ty * 4 + i];
            #pragma unroll
            for (int i = 0; i < 4; i++) br[i] = Bs[kk][tx * 4 + i];
            #pragma unroll
            for (int i = 0; i < 4; i++)
                #pragma unroll
                for (int jj = 0; jj < 4; jj++)
                    acc[i][jj] = fmaf(ar[i], br[jj], acc[i][jj]);
        }
        __syncthreads();
    }

    float bv[4];
    #pragma unroll
    for (int jj = 0; jj < 4; jj++) bv[jj] = bias[bn + tx * 4 + jj];

    #pragma unroll
    for (int i = 0; i < 4; i++) {
        #pragma unroll
        for (int jj = 0; jj < 4; jj++) {
            C[(size_t)(bm + ty * 4 + i) * N + (bn + tx * 4 + jj)] = acc[i][jj] + bv[jj];
        }
    }
}

// ---------------------------------------------------------------------------
// Scan-kernel helpers
// ---------------------------------------------------------------------------
#define FMA2(acc, a, b) \
    asm("fma.rn.f32x2 %0, %1, %2, %0;" : "+l"(acc) : "l"(a), "l"(b))

__device__ __forceinline__ void mbar_wait(uint32_t mbar, uint32_t parity) {
    asm volatile(
        "{\n\t"
        ".reg .pred P1;\n\t"
        "WAIT_LOOP_%=:\n\t"
        "mbarrier.try_wait.parity.acquire.cta.shared::cta.b64 P1, [%0], %1, 0x989680;\n\t"
        "@P1 bra.uni WAIT_DONE_%=;\n\t"
        "bra.uni WAIT_LOOP_%=;\n\t"
        "WAIT_DONE_%=:\n\t"
        "}"
        :: "r"(mbar), "r"(parity) : "memory");
}

__device__ __forceinline__ void mbar_expect(uint32_t mbar) {
    asm volatile("mbarrier.arrive.expect_tx.shared.b64 _, [%0], 2048;"
                 :: "r"(mbar) : "memory");
}

__device__ __forceinline__ uint32_t mapa_rank(uint32_t laddr, uint32_t rnk) {
    uint32_t r;
    asm("mapa.shared::cluster.u32 %0, %1, %2;" : "=r"(r) : "r"(laddr), "r"(rnk));
    return r;
}

__device__ __forceinline__ void st_async_f32(uint32_t raddr, float v, uint32_t rmbar) {
    asm volatile(
        "st.async.shared::cluster.mbarrier::complete_tx::bytes.b32 [%0], %1, [%2];"
        :: "r"(raddr), "r"(__float_as_uint(v)), "r"(rmbar) : "memory");
}

// 64-wide partial dot with packed f32x2 FMAs; chunk-rotated indices keep the
// 8 chunk-lanes of a warp on disjoint smem banks per LDS.128.
__device__ __forceinline__ float dot64(const ulonglong2* __restrict__ h2,
                                       const ulonglong2* __restrict__ w2,
                                       int chunk)
{
    unsigned long long aA = 0ull, aB = 0ull, aC = 0ull, aD = 0ull;
    #pragma unroll
    for (int q = 0; q < 16; q++) {
        int i4 = chunk * 16 + ((q + chunk) & 15);
        ulonglong2 hv = h2[i4];
        ulonglong2 wv = w2[q];
        if (q & 1) { FMA2(aC, wv.x, hv.x); FMA2(aD, wv.y, hv.y); }
        else       { FMA2(aA, wv.x, hv.x); FMA2(aB, wv.y, hv.y); }
    }
    float l0, h0, l1, h1, l2, h2f, l3, h3;
    asm("mov.b64 {%0, %1}, %2;" : "=f"(l0), "=f"(h0) : "l"(aA));
    asm("mov.b64 {%0, %1}, %2;" : "=f"(l1), "=f"(h1) : "l"(aB));
    asm("mov.b64 {%0, %1}, %2;" : "=f"(l2), "=f"(h2f) : "l"(aC));
    asm("mov.b64 {%0, %1}, %2;" : "=f"(l3), "=f"(h3) : "l"(aD));
    return ((l0 + h0) + (l1 + h1)) + ((l2 + h2f) + (l3 + h3));
}

// ---------------------------------------------------------------------------
// Serial recurrence, 8-CTA cluster, mbarrier/st.async pipeline (no cluster
// barrier in the loop). CTA c owns h rows [c*64,(c+1)*64); thread (jl,chunk)
// computes the chunk-th 64-wide slice of row j's dot, shfl-reduces over the 8
// chunk lanes, and st.async-delivers h[j] into peer CTA `chunk`'s next buffer,
// bumping that CTA's full-mbarrier tx count. Double-buffered; a local
// __syncthreads() between the read phase and the stores provides the
// anti-dependency that makes 2 buffers sufficient.
// ---------------------------------------------------------------------------
__global__ void __cluster_dims__(8, 1, 1) __launch_bounds__(512, 1)
rnn_scan_kernel(const float* __restrict__ Wh,
                const float* __restrict__ A,
                float* __restrict__ H)
{
    __shared__ __align__(16) float hbuf[2][HID];
    __shared__ __align__(8) unsigned long long mbar[2];

    const int tid = threadIdx.x;
    uint32_t rank;
    asm("mov.u32 %0, %%cluster_ctarank;" : "=r"(rank));

    const int chunk = tid & 7;
    const int jl = tid >> 3;
    const int j = (int)rank * 64 + jl;

    // Pack this thread's 64 Wh weights as 16 x (2 x f32x2), rotated per chunk.
    ulonglong2 w2[16];
    const ulonglong2* Wh2 = (const ulonglong2*)Wh;
    #pragma unroll
    for (int q = 0; q < 16; q++) {
        int i4 = chunk * 16 + ((q + chunk) & 15);
        w2[q] = Wh2[(size_t)j * 128 + i4];
    }

    const ulonglong2* h2_0 = (const ulonglong2*)hbuf[0];
    const ulonglong2* h2_1 = (const ulonglong2*)hbuf[1];

    // h0 = 0 (buffer 1 is fully overwritten by stores before first read).
    hbuf[0][tid] = 0.0f;

    const uint32_t mb0 = (uint32_t)__cvta_generic_to_shared(&mbar[0]);
    const uint32_t mb1 = (uint32_t)__cvta_generic_to_shared(&mbar[1]);

    if (tid == 0) {
        asm volatile("mbarrier.init.shared.b64 [%0], 1;" :: "r"(mb0) : "memory");
        asm volatile("mbarrier.init.shared.b64 [%0], 1;" :: "r"(mb1) : "memory");
    }
    __syncthreads();
    if (tid == 0) {            // pre-arm phase 0 of both buffers
        mbar_expect(mb0);
        mbar_expect(mb1);
    }

    // Remote targets in CTA `chunk` (same smem offsets, mapa'd once).
    const uint32_t r_h0  = mapa_rank((uint32_t)__cvta_generic_to_shared(&hbuf[0][j]), (uint32_t)chunk);
    const uint32_t r_h1  = mapa_rank((uint32_t)__cvta_generic_to_shared(&hbuf[1][j]), (uint32_t)chunk);
    const uint32_t r_mb0 = mapa_rank(mb0, (uint32_t)chunk);
    const uint32_t r_mb1 = mapa_rank(mb1, (uint32_t)chunk);

    // All CTAs' mbarriers armed and hbuf[0] zeroed before any remote store.
    asm volatile("barrier.cluster.arrive.aligned;" ::: "memory");
    asm volatile("barrier.cluster.wait.aligned;"   ::: "memory");

    uint32_t p0 = 0, p1 = 0;

    // 2-deep A prefetch (g_A is padded by 2 rows).
    const float* Ap = A + j;
    float a_cur = Ap[0];
    float a_nxt = Ap[HID];
    Ap += 2 * HID;

    const unsigned mask = 0xffffffffu;

    for (int t = 0; t < SEQ_LEN; t += 2) {
        // ---------- even step t: read hbuf[0], deliver into hbuf[1]/mb1 ----------
        if (t > 0) {
            mbar_wait(mb0, p0);
            p0 ^= 1;
            if (tid == 0) mbar_expect(mb0);   // re-arm next phase of buffer 0
        }
        float a_new0 = Ap[0];                 // prefetch A[t+2]

        float acc = dot64(h2_0, w2, chunk);
        __syncthreads();                       // all reads of hbuf[0] done
        acc += __shfl_xor_sync(mask, acc, 1);
        acc += __shfl_xor_sync(mask, acc, 2);
        acc += __shfl_xor_sync(mask, acc, 4);
        float hn = tanhf(acc + a_cur);

        st_async_f32(r_h1, hn, r_mb1);
        if (chunk == 0) H[t * HID + j] = hn;
        a_cur = a_nxt; a_nxt = a_new0;

        // ---------- odd step t+1: read hbuf[1], deliver into hbuf[0]/mb0 ----------
        mbar_wait(mb1, p1);
        p1 ^= 1;
        if (tid == 0) mbar_expect(mb1);
        float a_new1 = Ap[HID];               // prefetch A[t+3]

        acc = dot64(h2_1, w2, chunk);
        __syncthreads();                       // all reads of hbuf[1] done
        acc += __shfl_xor_sync(mask, acc, 1);
        acc += __shfl_xor_sync(mask, acc, 2);
        acc += __shfl_xor_sync(mask, acc, 4);
        hn = tanhf(acc + a_cur);

        if (t + 2 < SEQ_LEN) st_async_f32(r_h0, hn, r_mb0);  // skip at final step
        if (chunk == 0) H[(t + 1) * HID + j] = hn;
        a_cur = a_nxt; a_nxt = a_new1;

        Ap += 2 * HID;
    }

    // No CTA may exit while peers could still have traffic targeting its smem.
    asm volatile("barrier.cluster.arrive.aligned;" ::: "memory");
    asm volatile("barrier.cluster.wait.aligned;"   ::: "memory");
}

// ---------------------------------------------------------------------------
// Launch: A-GEMM -> serial scan -> Y-GEMM (graph-capturable, no allocs).
// ---------------------------------------------------------------------------
extern "C" void kernel_launch(void* const* d_in, const int* in_sizes, int n_in,
                              void* d_out, int out_size)
{
    const float* x  = (const float*)d_in[0];   // [32768, 256]
    const float* Wx = (const float*)d_in[1];   // [512, 256]
    const float* Wh = (const float*)d_in[2];   // [512, 512]
    const float* Wy = (const float*)d_in[3];   // [256, 512]
    const float* bh = (const float*)d_in[4];   // [512]
    const float* by = (const float*)d_in[5];   // [256]
    float* y = (float*)d_out;                  // [32768*256]

    float* A;
    float* H;
    cudaGetSymbolAddress((void**)&A, g_A);
    cudaGetSymbolAddress((void**)&H, g_H);

    // A = X @ Wx^T + bh : M=SEQ_LEN, N=HID, K=IN_SZ
    gemm_abt_bias<<<dim3(HID / 64, SEQ_LEN / 64), 256>>>(
        x, Wx, bh, A, SEQ_LEN, HID, IN_SZ);

    // Serial scan: 1 cluster of 8 CTAs, 512 threads each.
    rnn_scan_kernel<<<8, 512>>>(Wh, A, H);

    // Y = H @ Wy^T + by : M=SEQ_LEN, N=OUT_SZ, K=HID
    gemm_abt_bias<<<dim3(OUT_SZ / 64, SEQ_LEN / 64), 256>>>(
        H, Wy, by, y, SEQ_LEN, OUT_SZ, HID);
}